// round 16
// baseline (speedup 1.0000x reference)
#include <cuda_runtime.h>
#include <cuda_fp16.h>

#define MAXN 50000
#define MAXE 800000
#define DINC 128
#define DHC  128
#define DOUTC 64
#define SCHUNK 256
#define MAXNB ((MAXN + SCHUNK - 1) / SCHUNK)

// ---- scratch (static device globals; no allocation allowed) ----
__device__ int    g_deg[MAXN];
__device__ float  g_dinv[MAXN];
__device__ int    g_offs[MAXN + 1];
__device__ int    g_cursor[MAXN];
__device__ int    g_bsrc[MAXE];
__device__ int    g_beid[MAXE];          // original edge id per bucket slot
__device__ int    g_bdst[MAXE];          // dst node per bucket slot (sorted-contiguous)
__device__ int    g_bsum[MAXNB];
__device__ int    g_bpre[MAXNB];
__device__ __half g_xw1h[MAXN * DHC];    // fp16: gathered by agg128
__device__ float  g_h1 [MAXN * DHC];     // fp32: dense-read by GEMM2 only
__device__ __half g_xw2h[MAXN * DOUTC];  // fp16: gathered by agg64
__device__ __half g_h2h[MAXN * DOUTC];   // fp16: gathered by scorer

// ---------------- small helpers ----------------
__device__ __forceinline__ float4 f4fma(float4 a, float s, float4 acc) {
    acc.x += a.x * s; acc.y += a.y * s; acc.z += a.z * s; acc.w += a.w * s;
    return acc;
}
__device__ __forceinline__ float4 h4_to_f4(unsigned lo_u, unsigned hi_u) {
    half2 lo = *reinterpret_cast<half2*>(&lo_u);
    half2 hi = *reinterpret_cast<half2*>(&hi_u);
    float2 a = __half22float2(lo), b = __half22float2(hi);
    return make_float4(a.x, a.y, b.x, b.y);
}
__device__ __forceinline__ uint2 f4_to_h4(float4 v) {
    half2 lo = __floats2half2_rn(v.x, v.y);
    half2 hi = __floats2half2_rn(v.z, v.w);
    uint2 p;
    p.x = *reinterpret_cast<unsigned*>(&lo);
    p.y = *reinterpret_cast<unsigned*>(&hi);
    return p;
}

// ---------------- degree (1 edge/thread — measured best) ----------------
__global__ void k_deg(const int* __restrict__ dst, int* deg, int E) {
    int e = blockIdx.x * blockDim.x + threadIdx.x;
    if (e < E) atomicAdd(&deg[dst[e]], 1);
}

// ---------------- two-level scan: A) per-block sums ----------------
__global__ void k_scan_a(const int* __restrict__ deg, int* __restrict__ bsum, int n) {
    __shared__ int s[SCHUNK];
    int idx = blockIdx.x * SCHUNK + threadIdx.x;
    s[threadIdx.x] = (idx < n) ? deg[idx] : 0;
    __syncthreads();
    for (int d = SCHUNK / 2; d > 0; d >>= 1) {
        if (threadIdx.x < d) s[threadIdx.x] += s[threadIdx.x + d];
        __syncthreads();
    }
    if (threadIdx.x == 0) bsum[blockIdx.x] = s[0];
}

// ---------------- B) single small block scans block sums; writes offs[n] ----------------
__global__ void k_scan_b(const int* __restrict__ bsum, int* __restrict__ bpre,
                         int* __restrict__ offs, int nb, int n) {
    const int T = 1024;
    __shared__ int s[T];
    int tid = threadIdx.x;
    int v = (tid < nb) ? bsum[tid] : 0;
    s[tid] = v;
    __syncthreads();
    for (int d = 1; d < T; d <<= 1) {
        int t = 0;
        if (tid >= d) t = s[tid - d];
        __syncthreads();
        if (tid >= d) s[tid] += t;
        __syncthreads();
    }
    if (tid < nb) bpre[tid] = s[tid] - v;   // exclusive prefix
    if (tid == T - 1) offs[n] = s[T - 1];   // total = E
}

// ---------------- C) per-chunk exclusive scan; writes offs, cursor, dinv ----------------
__global__ void k_scan_c(const int* __restrict__ deg, const int* __restrict__ bpre,
                         int* __restrict__ offs, int* __restrict__ cursor,
                         float* __restrict__ dinv, int n) {
    __shared__ int s[SCHUNK];
    int idx = blockIdx.x * SCHUNK + threadIdx.x;
    int dg = (idx < n) ? deg[idx] : 0;
    s[threadIdx.x] = dg;
    __syncthreads();
    for (int d = 1; d < SCHUNK; d <<= 1) {
        int t = 0;
        if (threadIdx.x >= d) t = s[threadIdx.x - d];
        __syncthreads();
        if (threadIdx.x >= d) s[threadIdx.x] += t;
        __syncthreads();
    }
    if (idx < n) {
        int off = bpre[blockIdx.x] + s[threadIdx.x] - dg;  // exclusive
        offs[idx] = off;
        cursor[idx] = off;
        dinv[idx] = rsqrtf((float)(dg + 1));  // +1 self-loop
    }
}

// ---------------- bucket edges by dst; also record edge id + dst per slot ----------------
__global__ void k_bucket(const int* __restrict__ src, const int* __restrict__ dst,
                         int* cursor, int* __restrict__ bsrc,
                         int* __restrict__ beid, int* __restrict__ bdst, int E) {
    int e = blockIdx.x * blockDim.x + threadIdx.x;
    if (e >= E) return;
    int d = dst[e];
    int p = atomicAdd(&cursor[d], 1);
    bsrc[p] = src[e];
    beid[p] = e;
    bdst[p] = d;
}

// ---------------- GEMM: out[n,NCOL] = act(X[n,128]) @ W[128,NCOL], fp16 epilogue ----------------
template <int NCOL, bool RELU_IN>
__global__ __launch_bounds__(256) void k_gemm(const float* __restrict__ X,
                                              const float* __restrict__ W,
                                              __half* __restrict__ out, int n) {
    constexpr int KT = 16;
    constexpr int COLG = NCOL / 4;
    constexpr int RTH = 256 / COLG;
    constexpr int RPT = 64 / RTH;
    __shared__ float Xs[KT][68];
    __shared__ float Ws[KT][NCOL];

    int tid = threadIdx.x;
    int row0 = blockIdx.x * 64;
    int cx = tid % COLG;
    int ry = tid / COLG;

    float4 acc[RPT];
#pragma unroll
    for (int j = 0; j < RPT; j++) acc[j] = make_float4(0.f, 0.f, 0.f, 0.f);

    for (int k0 = 0; k0 < 128; k0 += KT) {
        __syncthreads();
        {
            int rr = tid >> 2;
            int kv = (tid & 3) * 4;
            int row = row0 + rr;
            float4 v = make_float4(0.f, 0.f, 0.f, 0.f);
            if (row < n) v = __ldg(reinterpret_cast<const float4*>(X + row * 128 + k0 + kv));
            if (RELU_IN) {
                v.x = fmaxf(v.x, 0.f); v.y = fmaxf(v.y, 0.f);
                v.z = fmaxf(v.z, 0.f); v.w = fmaxf(v.w, 0.f);
            }
            Xs[kv + 0][rr] = v.x; Xs[kv + 1][rr] = v.y;
            Xs[kv + 2][rr] = v.z; Xs[kv + 3][rr] = v.w;
        }
#pragma unroll
        for (int lin = tid; lin < KT * COLG; lin += 256) {
            int kk = lin / COLG;
            int c = lin % COLG;
            *reinterpret_cast<float4*>(&Ws[kk][c * 4]) =
                __ldg(reinterpret_cast<const float4*>(W + (k0 + kk) * NCOL + c * 4));
        }
        __syncthreads();
#pragma unroll
        for (int kk = 0; kk < KT; kk++) {
            float4 w = *reinterpret_cast<float4*>(&Ws[kk][cx * 4]);
#pragma unroll
            for (int rv = 0; rv < RPT / 4; rv++) {
                float4 xr = *reinterpret_cast<float4*>(&Xs[kk][ry * RPT + rv * 4]);
                acc[rv * 4 + 0] = f4fma(w, xr.x, acc[rv * 4 + 0]);
                acc[rv * 4 + 1] = f4fma(w, xr.y, acc[rv * 4 + 1]);
                acc[rv * 4 + 2] = f4fma(w, xr.z, acc[rv * 4 + 2]);
                acc[rv * 4 + 3] = f4fma(w, xr.w, acc[rv * 4 + 3]);
            }
        }
    }
#pragma unroll
    for (int j = 0; j < RPT; j++) {
        int row = row0 + ry * RPT + j;
        if (row < n)
            *reinterpret_cast<uint2*>(out + (size_t)row * NCOL + cx * 4) = f4_to_h4(acc[j]);
    }
}

// ---------------- gather aggregation, d=128: fp16 gathers, fp32 accum, fp32 h1 out ----------------
__global__ __launch_bounds__(256) void k_agg128(
    const __half* __restrict__ xw, const int* __restrict__ offs,
    const int* __restrict__ bsrc, const float* __restrict__ dinv,
    const float4* __restrict__ bias, float4* __restrict__ h, int n) {
    int t = blockIdx.x * blockDim.x + threadIdx.x;
    int node = t >> 5;
    int lane = t & 31;
    if (node >= n) return;
    float dn = __ldg(dinv + node);
    float4 bb = __ldg(bias + lane);
    uint2 sp = __ldg(reinterpret_cast<const uint2*>(xw + (size_t)node * 128 + lane * 4));
    float4 acc = f4fma(h4_to_f4(sp.x, sp.y), dn * dn, bb);
    int beg = __ldg(offs + node), end = __ldg(offs + node + 1);
    int j = beg;
    for (; j + 1 < end; j += 2) {
        int s0 = __ldg(bsrc + j), s1 = __ldg(bsrc + j + 1);
        float n0 = __ldg(dinv + s0) * dn, n1 = __ldg(dinv + s1) * dn;
        uint2 p0 = __ldg(reinterpret_cast<const uint2*>(xw + (size_t)s0 * 128 + lane * 4));
        uint2 p1 = __ldg(reinterpret_cast<const uint2*>(xw + (size_t)s1 * 128 + lane * 4));
        acc = f4fma(h4_to_f4(p0.x, p0.y), n0, acc);
        acc = f4fma(h4_to_f4(p1.x, p1.y), n1, acc);
    }
    if (j < end) {
        int s0 = __ldg(bsrc + j);
        uint2 p0 = __ldg(reinterpret_cast<const uint2*>(xw + (size_t)s0 * 128 + lane * 4));
        acc = f4fma(h4_to_f4(p0.x, p0.y), __ldg(dinv + s0) * dn, acc);
    }
    h[(size_t)node * 32 + lane] = acc;
}

// ---------------- gather aggregation, d=64: fp16 gathers, fp32 accum, fp16 h2 out ----------------
__global__ __launch_bounds__(256) void k_agg64(
    const __half* __restrict__ xw, const int* __restrict__ offs,
    const int* __restrict__ bsrc, const float* __restrict__ dinv,
    const float2* __restrict__ bias, __half* __restrict__ h, int n) {
    int t = blockIdx.x * blockDim.x + threadIdx.x;
    int node = t >> 5;
    int lane = t & 31;
    if (node >= n) return;
    float dn = __ldg(dinv + node);
    float2 bb = __ldg(bias + lane);
    float2 sv = __half22float2(__ldg(reinterpret_cast<const half2*>(xw + (size_t)node * 64 + lane * 2)));
    float s = dn * dn;
    float2 acc = make_float2(sv.x * s + bb.x, sv.y * s + bb.y);
    int beg = __ldg(offs + node), end = __ldg(offs + node + 1);
    int j = beg;
    for (; j + 1 < end; j += 2) {
        int s0 = __ldg(bsrc + j), s1 = __ldg(bsrc + j + 1);
        float n0 = __ldg(dinv + s0) * dn, n1 = __ldg(dinv + s1) * dn;
        float2 a = __half22float2(__ldg(reinterpret_cast<const half2*>(xw + (size_t)s0 * 64 + lane * 2)));
        float2 b = __half22float2(__ldg(reinterpret_cast<const half2*>(xw + (size_t)s1 * 64 + lane * 2)));
        acc.x += a.x * n0 + b.x * n1;
        acc.y += a.y * n0 + b.y * n1;
    }
    if (j < end) {
        int s0 = __ldg(bsrc + j);
        float n0 = __ldg(dinv + s0) * dn;
        float2 a = __half22float2(__ldg(reinterpret_cast<const half2*>(xw + (size_t)s0 * 64 + lane * 2)));
        acc.x += a.x * n0; acc.y += a.y * n0;
    }
    *reinterpret_cast<half2*>(h + (size_t)node * 64 + lane * 2) = __floats2half2_rn(acc.x, acc.y);
}

// ---------------- edge scorer: bucket (dst-sorted) order; flat 8 lanes/edge ----------------
// Consecutive slots share dst -> dst-row loads broadcast/L1-hit instead of random L2.
__global__ __launch_bounds__(256) void k_score(const __half* __restrict__ h2,
                                               const int* __restrict__ bsrc,
                                               const int* __restrict__ beid,
                                               const int* __restrict__ bdst,
                                               float* __restrict__ out, int E) {
    int t = blockIdx.x * blockDim.x + threadIdx.x;
    int p = t >> 3;
    int lane = t & 7;
    if (p >= E) return;
    int s = __ldg(bsrc + p);
    int d = __ldg(bdst + p);
    uint4 pa = __ldg(reinterpret_cast<const uint4*>(h2 + (size_t)s * 64 + lane * 8));
    uint4 pb = __ldg(reinterpret_cast<const uint4*>(h2 + (size_t)d * 64 + lane * 8));
    float4 a0 = h4_to_f4(pa.x, pa.y);
    float4 a1 = h4_to_f4(pa.z, pa.w);
    float4 b0 = h4_to_f4(pb.x, pb.y);
    float4 b1 = h4_to_f4(pb.z, pb.w);
    float v = a0.x * b0.x + a0.y * b0.y + a0.z * b0.z + a0.w * b0.w
            + a1.x * b1.x + a1.y * b1.y + a1.z * b1.z + a1.w * b1.w;
#pragma unroll
    for (int off = 4; off; off >>= 1) v += __shfl_xor_sync(0xFFFFFFFFu, v, off);
    if (lane == 0) out[__ldg(beid + p)] = v;
}

static inline int cdiv(long long a, int b) { return (int)((a + b - 1) / b); }

extern "C" void kernel_launch(void* const* d_in, const int* in_sizes, int n_in,
                              void* d_out, int out_size) {
    const float* x   = (const float*)d_in[0];
    const int*   src = (const int*)  d_in[1];
    const int*   dst = (const int*)  d_in[2];
    const float* W1  = (const float*)d_in[3];
    const float* b1  = (const float*)d_in[4];
    const float* W2  = (const float*)d_in[5];
    const float* b2  = (const float*)d_in[6];
    float* score = (float*)d_out;

    int n = in_sizes[0] / DINC;
    int E = in_sizes[1];
    int nb = cdiv(n, SCHUNK);

    void *p_deg, *p_dinv, *p_offs, *p_cursor, *p_bsrc, *p_beid, *p_bdst,
         *p_bsum, *p_bpre, *p_xw1, *p_h1, *p_xw2, *p_h2;
    cudaGetSymbolAddress(&p_deg,    g_deg);
    cudaGetSymbolAddress(&p_dinv,   g_dinv);
    cudaGetSymbolAddress(&p_offs,   g_offs);
    cudaGetSymbolAddress(&p_cursor, g_cursor);
    cudaGetSymbolAddress(&p_bsrc,   g_bsrc);
    cudaGetSymbolAddress(&p_beid,   g_beid);
    cudaGetSymbolAddress(&p_bdst,   g_bdst);
    cudaGetSymbolAddress(&p_bsum,   g_bsum);
    cudaGetSymbolAddress(&p_bpre,   g_bpre);
    cudaGetSymbolAddress(&p_xw1,    g_xw1h);
    cudaGetSymbolAddress(&p_h1,     g_h1);
    cudaGetSymbolAddress(&p_xw2,    g_xw2h);
    cudaGetSymbolAddress(&p_h2,     g_h2h);
    int*    deg    = (int*)p_deg;
    float*  dinv   = (float*)p_dinv;
    int*    offs   = (int*)p_offs;
    int*    cursor = (int*)p_cursor;
    int*    bsrc   = (int*)p_bsrc;
    int*    beid   = (int*)p_beid;
    int*    bdst   = (int*)p_bdst;
    int*    bsum   = (int*)p_bsum;
    int*    bpre   = (int*)p_bpre;
    __half* xw1    = (__half*)p_xw1;
    float*  h1     = (float*)p_h1;
    __half* xw2    = (__half*)p_xw2;
    __half* h2     = (__half*)p_h2;

    // one-time host resources (no device allocation; streams/events only)
    static cudaStream_t s2 = nullptr;
    static cudaEvent_t evFork = nullptr, evJoin = nullptr;
    if (!s2) {
        cudaStreamCreateWithFlags(&s2, cudaStreamNonBlocking);
        cudaEventCreateWithFlags(&evFork, cudaEventDisableTiming);
        cudaEventCreateWithFlags(&evJoin, cudaEventDisableTiming);
    }

    const int B = 256;

    // ---- fork: GEMM1 (features only) on s2, CSR build (graph only) on capture stream ----
    cudaEventRecord(evFork, 0);
    cudaStreamWaitEvent(s2, evFork, 0);
    k_gemm<DHC, false><<<cdiv(n, 64), B, 0, s2>>>(x, W1, xw1, n);
    cudaEventRecord(evJoin, s2);

    // CSR build — parallel two-level scan
    cudaMemsetAsync(deg, 0, (size_t)n * sizeof(int));
    k_deg<<<cdiv(E, B), B>>>(dst, deg, E);
    k_scan_a<<<nb, SCHUNK>>>(deg, bsum, n);
    k_scan_b<<<1, 1024>>>(bsum, bpre, offs, nb, n);
    k_scan_c<<<nb, SCHUNK>>>(deg, bpre, offs, cursor, dinv, n);
    k_bucket<<<cdiv(E, B), B>>>(src, dst, cursor, bsrc, beid, bdst, E);

    // ---- join: agg128 needs bucket (this stream) + gemm1 (s2) ----
    cudaStreamWaitEvent(0, evJoin, 0);
    k_agg128<<<cdiv((long long)n * 32, B), B>>>(xw1, offs, bsrc, dinv,
                                                (const float4*)b1, (float4*)h1, n);

    // ---- layer 2 (relu fused into GEMM input; fp16 intermediates) ----
    k_gemm<DOUTC, true><<<cdiv(n, 64), B>>>(h1, W2, xw2, n);
    k_agg64<<<cdiv((long long)n * 32, B), B>>>(xw2, offs, bsrc, dinv,
                                               (const float2*)b2, h2, n);

    // ---- edge scores: dst-sorted bucket order for dst-row locality ----
    k_score<<<cdiv((long long)E * 8, B), B>>>(h2, bsrc, beid, bdst, score, E);
}

// round 17
// speedup vs baseline: 1.6150x; 1.6150x over previous
#include <cuda_runtime.h>
#include <cuda_fp16.h>

#define MAXN 50000
#define MAXE 800000
#define DINC 128
#define DHC  128
#define DOUTC 64
#define SCHUNK 256
#define MAXNB ((MAXN + SCHUNK - 1) / SCHUNK)

// ---- scratch (static device globals; no allocation allowed) ----
__device__ int    g_deg[MAXN];
__device__ float  g_dinv[MAXN];
__device__ int    g_offs[MAXN + 1];
__device__ int    g_cursor[MAXN];
__device__ int    g_bsrc[MAXE];
__device__ int    g_bsum[MAXNB];
__device__ int    g_bpre[MAXNB];
__device__ __half g_xw1h[MAXN * DHC];    // fp16: gathered by agg128
__device__ __half g_h1h [MAXN * DHC];    // fp16: dense write (agg128) + dense read (GEMM2)
__device__ __half g_xw2h[MAXN * DOUTC];  // fp16: gathered by agg64
__device__ __half g_h2h[MAXN * DOUTC];   // fp16: gathered by scorer

// ---------------- small helpers ----------------
__device__ __forceinline__ float4 f4fma(float4 a, float s, float4 acc) {
    acc.x += a.x * s; acc.y += a.y * s; acc.z += a.z * s; acc.w += a.w * s;
    return acc;
}
__device__ __forceinline__ float4 h4_to_f4(unsigned lo_u, unsigned hi_u) {
    half2 lo = *reinterpret_cast<half2*>(&lo_u);
    half2 hi = *reinterpret_cast<half2*>(&hi_u);
    float2 a = __half22float2(lo), b = __half22float2(hi);
    return make_float4(a.x, a.y, b.x, b.y);
}
__device__ __forceinline__ uint2 f4_to_h4(float4 v) {
    half2 lo = __floats2half2_rn(v.x, v.y);
    half2 hi = __floats2half2_rn(v.z, v.w);
    uint2 p;
    p.x = *reinterpret_cast<unsigned*>(&lo);
    p.y = *reinterpret_cast<unsigned*>(&hi);
    return p;
}

// ---------------- degree (1 edge/thread — measured best) ----------------
__global__ void k_deg(const int* __restrict__ dst, int* deg, int E) {
    int e = blockIdx.x * blockDim.x + threadIdx.x;
    if (e < E) atomicAdd(&deg[dst[e]], 1);
}

// ---------------- two-level scan: A) per-block sums ----------------
__global__ void k_scan_a(const int* __restrict__ deg, int* __restrict__ bsum, int n) {
    __shared__ int s[SCHUNK];
    int idx = blockIdx.x * SCHUNK + threadIdx.x;
    s[threadIdx.x] = (idx < n) ? deg[idx] : 0;
    __syncthreads();
    for (int d = SCHUNK / 2; d > 0; d >>= 1) {
        if (threadIdx.x < d) s[threadIdx.x] += s[threadIdx.x + d];
        __syncthreads();
    }
    if (threadIdx.x == 0) bsum[blockIdx.x] = s[0];
}

// ---------------- B) single small block scans block sums; writes offs[n] ----------------
__global__ void k_scan_b(const int* __restrict__ bsum, int* __restrict__ bpre,
                         int* __restrict__ offs, int nb, int n) {
    const int T = 1024;
    __shared__ int s[T];
    int tid = threadIdx.x;
    int v = (tid < nb) ? bsum[tid] : 0;
    s[tid] = v;
    __syncthreads();
    for (int d = 1; d < T; d <<= 1) {
        int t = 0;
        if (tid >= d) t = s[tid - d];
        __syncthreads();
        if (tid >= d) s[tid] += t;
        __syncthreads();
    }
    if (tid < nb) bpre[tid] = s[tid] - v;   // exclusive prefix
    if (tid == T - 1) offs[n] = s[T - 1];   // total = E
}

// ---------------- C) per-chunk exclusive scan; writes offs, cursor, dinv ----------------
__global__ void k_scan_c(const int* __restrict__ deg, const int* __restrict__ bpre,
                         int* __restrict__ offs, int* __restrict__ cursor,
                         float* __restrict__ dinv, int n) {
    __shared__ int s[SCHUNK];
    int idx = blockIdx.x * SCHUNK + threadIdx.x;
    int dg = (idx < n) ? deg[idx] : 0;
    s[threadIdx.x] = dg;
    __syncthreads();
    for (int d = 1; d < SCHUNK; d <<= 1) {
        int t = 0;
        if (threadIdx.x >= d) t = s[threadIdx.x - d];
        __syncthreads();
        if (threadIdx.x >= d) s[threadIdx.x] += t;
        __syncthreads();
    }
    if (idx < n) {
        int off = bpre[blockIdx.x] + s[threadIdx.x] - dg;  // exclusive
        offs[idx] = off;
        cursor[idx] = off;
        dinv[idx] = rsqrtf((float)(dg + 1));  // +1 self-loop
    }
}

// ---------------- bucket edges by dst (1 edge/thread, 1 store — measured best) ----------------
__global__ void k_bucket(const int* __restrict__ src, const int* __restrict__ dst,
                         int* cursor, int* __restrict__ bsrc, int E) {
    int e = blockIdx.x * blockDim.x + threadIdx.x;
    if (e >= E) return;
    int d = dst[e];
    int p = atomicAdd(&cursor[d], 1);
    bsrc[p] = src[e];
}

// ---------------- GEMM1: out[n,128] = X_fp32[n,128] @ W, fp16 epilogue ----------------
__global__ __launch_bounds__(256) void k_gemm1(const float* __restrict__ X,
                                               const float* __restrict__ W,
                                               __half* __restrict__ out, int n) {
    constexpr int NCOL = DHC;
    constexpr int KT = 16;
    constexpr int COLG = NCOL / 4;
    constexpr int RTH = 256 / COLG;
    constexpr int RPT = 64 / RTH;
    __shared__ float Xs[KT][68];
    __shared__ float Ws[KT][NCOL];

    int tid = threadIdx.x;
    int row0 = blockIdx.x * 64;
    int cx = tid % COLG;
    int ry = tid / COLG;

    float4 acc[RPT];
#pragma unroll
    for (int j = 0; j < RPT; j++) acc[j] = make_float4(0.f, 0.f, 0.f, 0.f);

    for (int k0 = 0; k0 < 128; k0 += KT) {
        __syncthreads();
        {
            int rr = tid >> 2;
            int kv = (tid & 3) * 4;
            int row = row0 + rr;
            float4 v = make_float4(0.f, 0.f, 0.f, 0.f);
            if (row < n) v = __ldg(reinterpret_cast<const float4*>(X + row * 128 + k0 + kv));
            Xs[kv + 0][rr] = v.x; Xs[kv + 1][rr] = v.y;
            Xs[kv + 2][rr] = v.z; Xs[kv + 3][rr] = v.w;
        }
#pragma unroll
        for (int lin = tid; lin < KT * COLG; lin += 256) {
            int kk = lin / COLG;
            int c = lin % COLG;
            *reinterpret_cast<float4*>(&Ws[kk][c * 4]) =
                __ldg(reinterpret_cast<const float4*>(W + (k0 + kk) * NCOL + c * 4));
        }
        __syncthreads();
#pragma unroll
        for (int kk = 0; kk < KT; kk++) {
            float4 w = *reinterpret_cast<float4*>(&Ws[kk][cx * 4]);
#pragma unroll
            for (int rv = 0; rv < RPT / 4; rv++) {
                float4 xr = *reinterpret_cast<float4*>(&Xs[kk][ry * RPT + rv * 4]);
                acc[rv * 4 + 0] = f4fma(w, xr.x, acc[rv * 4 + 0]);
                acc[rv * 4 + 1] = f4fma(w, xr.y, acc[rv * 4 + 1]);
                acc[rv * 4 + 2] = f4fma(w, xr.z, acc[rv * 4 + 2]);
                acc[rv * 4 + 3] = f4fma(w, xr.w, acc[rv * 4 + 3]);
            }
        }
    }
#pragma unroll
    for (int j = 0; j < RPT; j++) {
        int row = row0 + ry * RPT + j;
        if (row < n)
            *reinterpret_cast<uint2*>(out + (size_t)row * NCOL + cx * 4) = f4_to_h4(acc[j]);
    }
}

// ---------------- GEMM2: out[n,64] = relu(H_fp16[n,128]) @ W, fp16 epilogue ----------------
__global__ __launch_bounds__(256) void k_gemm2(const __half* __restrict__ X,
                                               const float* __restrict__ W,
                                               __half* __restrict__ out, int n) {
    constexpr int NCOL = DOUTC;
    constexpr int KT = 16;
    constexpr int COLG = NCOL / 4;
    constexpr int RTH = 256 / COLG;
    constexpr int RPT = 64 / RTH;
    __shared__ float Xs[KT][68];
    __shared__ float Ws[KT][NCOL];

    int tid = threadIdx.x;
    int row0 = blockIdx.x * 64;
    int cx = tid % COLG;
    int ry = tid / COLG;

    float4 acc[RPT];
#pragma unroll
    for (int j = 0; j < RPT; j++) acc[j] = make_float4(0.f, 0.f, 0.f, 0.f);

    for (int k0 = 0; k0 < 128; k0 += KT) {
        __syncthreads();
        {
            int rr = tid >> 2;
            int kv = (tid & 3) * 4;
            int row = row0 + rr;
            float4 v = make_float4(0.f, 0.f, 0.f, 0.f);
            if (row < n) {
                uint2 p = __ldg(reinterpret_cast<const uint2*>(X + (size_t)row * 128 + k0 + kv));
                v = h4_to_f4(p.x, p.y);
            }
            // relu fused on load
            v.x = fmaxf(v.x, 0.f); v.y = fmaxf(v.y, 0.f);
            v.z = fmaxf(v.z, 0.f); v.w = fmaxf(v.w, 0.f);
            Xs[kv + 0][rr] = v.x; Xs[kv + 1][rr] = v.y;
            Xs[kv + 2][rr] = v.z; Xs[kv + 3][rr] = v.w;
        }
#pragma unroll
        for (int lin = tid; lin < KT * COLG; lin += 256) {
            int kk = lin / COLG;
            int c = lin % COLG;
            *reinterpret_cast<float4*>(&Ws[kk][c * 4]) =
                __ldg(reinterpret_cast<const float4*>(W + (k0 + kk) * NCOL + c * 4));
        }
        __syncthreads();
#pragma unroll
        for (int kk = 0; kk < KT; kk++) {
            float4 w = *reinterpret_cast<float4*>(&Ws[kk][cx * 4]);
#pragma unroll
            for (int rv = 0; rv < RPT / 4; rv++) {
                float4 xr = *reinterpret_cast<float4*>(&Xs[kk][ry * RPT + rv * 4]);
                acc[rv * 4 + 0] = f4fma(w, xr.x, acc[rv * 4 + 0]);
                acc[rv * 4 + 1] = f4fma(w, xr.y, acc[rv * 4 + 1]);
                acc[rv * 4 + 2] = f4fma(w, xr.z, acc[rv * 4 + 2]);
                acc[rv * 4 + 3] = f4fma(w, xr.w, acc[rv * 4 + 3]);
            }
        }
    }
#pragma unroll
    for (int j = 0; j < RPT; j++) {
        int row = row0 + ry * RPT + j;
        if (row < n)
            *reinterpret_cast<uint2*>(out + (size_t)row * NCOL + cx * 4) = f4_to_h4(acc[j]);
    }
}

// ---------------- gather aggregation, d=128: fp16 gathers, fp32 accum, fp16 h1 out ----------------
__global__ __launch_bounds__(256) void k_agg128(
    const __half* __restrict__ xw, const int* __restrict__ offs,
    const int* __restrict__ bsrc, const float* __restrict__ dinv,
    const float4* __restrict__ bias, __half* __restrict__ h, int n) {
    int t = blockIdx.x * blockDim.x + threadIdx.x;
    int node = t >> 5;
    int lane = t & 31;
    if (node >= n) return;
    float dn = __ldg(dinv + node);
    float4 bb = __ldg(bias + lane);
    uint2 sp = __ldg(reinterpret_cast<const uint2*>(xw + (size_t)node * 128 + lane * 4));
    float4 acc = f4fma(h4_to_f4(sp.x, sp.y), dn * dn, bb);
    int beg = __ldg(offs + node), end = __ldg(offs + node + 1);
    int j = beg;
    for (; j + 1 < end; j += 2) {
        int s0 = __ldg(bsrc + j), s1 = __ldg(bsrc + j + 1);
        float n0 = __ldg(dinv + s0) * dn, n1 = __ldg(dinv + s1) * dn;
        uint2 p0 = __ldg(reinterpret_cast<const uint2*>(xw + (size_t)s0 * 128 + lane * 4));
        uint2 p1 = __ldg(reinterpret_cast<const uint2*>(xw + (size_t)s1 * 128 + lane * 4));
        acc = f4fma(h4_to_f4(p0.x, p0.y), n0, acc);
        acc = f4fma(h4_to_f4(p1.x, p1.y), n1, acc);
    }
    if (j < end) {
        int s0 = __ldg(bsrc + j);
        uint2 p0 = __ldg(reinterpret_cast<const uint2*>(xw + (size_t)s0 * 128 + lane * 4));
        acc = f4fma(h4_to_f4(p0.x, p0.y), __ldg(dinv + s0) * dn, acc);
    }
    *reinterpret_cast<uint2*>(h + (size_t)node * 128 + lane * 4) = f4_to_h4(acc);
}

// ---------------- gather aggregation, d=64: fp16 gathers, fp32 accum, fp16 h2 out ----------------
__global__ __launch_bounds__(256) void k_agg64(
    const __half* __restrict__ xw, const int* __restrict__ offs,
    const int* __restrict__ bsrc, const float* __restrict__ dinv,
    const float2* __restrict__ bias, __half* __restrict__ h, int n) {
    int t = blockIdx.x * blockDim.x + threadIdx.x;
    int node = t >> 5;
    int lane = t & 31;
    if (node >= n) return;
    float dn = __ldg(dinv + node);
    float2 bb = __ldg(bias + lane);
    float2 sv = __half22float2(__ldg(reinterpret_cast<const half2*>(xw + (size_t)node * 64 + lane * 2)));
    float s = dn * dn;
    float2 acc = make_float2(sv.x * s + bb.x, sv.y * s + bb.y);
    int beg = __ldg(offs + node), end = __ldg(offs + node + 1);
    int j = beg;
    for (; j + 1 < end; j += 2) {
        int s0 = __ldg(bsrc + j), s1 = __ldg(bsrc + j + 1);
        float n0 = __ldg(dinv + s0) * dn, n1 = __ldg(dinv + s1) * dn;
        float2 a = __half22float2(__ldg(reinterpret_cast<const half2*>(xw + (size_t)s0 * 64 + lane * 2)));
        float2 b = __half22float2(__ldg(reinterpret_cast<const half2*>(xw + (size_t)s1 * 64 + lane * 2)));
        acc.x += a.x * n0 + b.x * n1;
        acc.y += a.y * n0 + b.y * n1;
    }
    if (j < end) {
        int s0 = __ldg(bsrc + j);
        float n0 = __ldg(dinv + s0) * dn;
        float2 a = __half22float2(__ldg(reinterpret_cast<const half2*>(xw + (size_t)s0 * 64 + lane * 2)));
        acc.x += a.x * n0; acc.y += a.y * n0;
    }
    *reinterpret_cast<half2*>(h + (size_t)node * 64 + lane * 2) = __floats2half2_rn(acc.x, acc.y);
}

// ---------------- edge scorer: fp16 h2, 8 lanes/edge, 16B loads (measured best) ----------------
__global__ __launch_bounds__(256) void k_score(const __half* __restrict__ h2,
                                               const int* __restrict__ src,
                                               const int* __restrict__ dst,
                                               float* __restrict__ out, int E) {
    int t = blockIdx.x * blockDim.x + threadIdx.x;
    int e = t >> 3;
    int lane = t & 7;
    if (e >= E) return;
    int s = __ldg(src + e);
    int d = __ldg(dst + e);
    uint4 pa = __ldg(reinterpret_cast<const uint4*>(h2 + (size_t)s * 64 + lane * 8));
    uint4 pb = __ldg(reinterpret_cast<const uint4*>(h2 + (size_t)d * 64 + lane * 8));
    float4 a0 = h4_to_f4(pa.x, pa.y);
    float4 a1 = h4_to_f4(pa.z, pa.w);
    float4 b0 = h4_to_f4(pb.x, pb.y);
    float4 b1 = h4_to_f4(pb.z, pb.w);
    float p = a0.x * b0.x + a0.y * b0.y + a0.z * b0.z + a0.w * b0.w
            + a1.x * b1.x + a1.y * b1.y + a1.z * b1.z + a1.w * b1.w;
#pragma unroll
    for (int off = 4; off; off >>= 1) p += __shfl_xor_sync(0xFFFFFFFFu, p, off);
    if (lane == 0) out[e] = p;
}

static inline int cdiv(long long a, int b) { return (int)((a + b - 1) / b); }

extern "C" void kernel_launch(void* const* d_in, const int* in_sizes, int n_in,
                              void* d_out, int out_size) {
    const float* x   = (const float*)d_in[0];
    const int*   src = (const int*)  d_in[1];
    const int*   dst = (const int*)  d_in[2];
    const float* W1  = (const float*)d_in[3];
    const float* b1  = (const float*)d_in[4];
    const float* W2  = (const float*)d_in[5];
    const float* b2  = (const float*)d_in[6];
    float* score = (float*)d_out;

    int n = in_sizes[0] / DINC;
    int E = in_sizes[1];
    int nb = cdiv(n, SCHUNK);

    void *p_deg, *p_dinv, *p_offs, *p_cursor, *p_bsrc, *p_bsum, *p_bpre,
         *p_xw1, *p_h1, *p_xw2, *p_h2;
    cudaGetSymbolAddress(&p_deg,    g_deg);
    cudaGetSymbolAddress(&p_dinv,   g_dinv);
    cudaGetSymbolAddress(&p_offs,   g_offs);
    cudaGetSymbolAddress(&p_cursor, g_cursor);
    cudaGetSymbolAddress(&p_bsrc,   g_bsrc);
    cudaGetSymbolAddress(&p_bsum,   g_bsum);
    cudaGetSymbolAddress(&p_bpre,   g_bpre);
    cudaGetSymbolAddress(&p_xw1,    g_xw1h);
    cudaGetSymbolAddress(&p_h1,     g_h1h);
    cudaGetSymbolAddress(&p_xw2,    g_xw2h);
    cudaGetSymbolAddress(&p_h2,     g_h2h);
    int*    deg    = (int*)p_deg;
    float*  dinv   = (float*)p_dinv;
    int*    offs   = (int*)p_offs;
    int*    cursor = (int*)p_cursor;
    int*    bsrc   = (int*)p_bsrc;
    int*    bsum   = (int*)p_bsum;
    int*    bpre   = (int*)p_bpre;
    __half* xw1    = (__half*)p_xw1;
    __half* h1     = (__half*)p_h1;
    __half* xw2    = (__half*)p_xw2;
    __half* h2     = (__half*)p_h2;

    // one-time host resources (no device allocation; streams/events only)
    static cudaStream_t s2 = nullptr;
    static cudaEvent_t evFork = nullptr, evJoin = nullptr;
    if (!s2) {
        cudaStreamCreateWithFlags(&s2, cudaStreamNonBlocking);
        cudaEventCreateWithFlags(&evFork, cudaEventDisableTiming);
        cudaEventCreateWithFlags(&evJoin, cudaEventDisableTiming);
    }

    const int B = 256;

    // ---- fork: GEMM1 (features only) on s2, CSR build (graph only) on capture stream ----
    cudaEventRecord(evFork, 0);
    cudaStreamWaitEvent(s2, evFork, 0);
    k_gemm1<<<cdiv(n, 64), B, 0, s2>>>(x, W1, xw1, n);
    cudaEventRecord(evJoin, s2);

    // CSR build — parallel two-level scan
    cudaMemsetAsync(deg, 0, (size_t)n * sizeof(int));
    k_deg<<<cdiv(E, B), B>>>(dst, deg, E);
    k_scan_a<<<nb, SCHUNK>>>(deg, bsum, n);
    k_scan_b<<<1, 1024>>>(bsum, bpre, offs, nb, n);
    k_scan_c<<<nb, SCHUNK>>>(deg, bpre, offs, cursor, dinv, n);
    k_bucket<<<cdiv(E, B), B>>>(src, dst, cursor, bsrc, E);

    // ---- join: agg128 needs bucket (this stream) + gemm1 (s2) ----
    cudaStreamWaitEvent(0, evJoin, 0);
    k_agg128<<<cdiv((long long)n * 32, B), B>>>(xw1, offs, bsrc, dinv,
                                                (const float4*)b1, h1, n);

    // ---- layer 2 (relu fused into GEMM2 load; all-fp16 intermediates) ----
    k_gemm2<<<cdiv(n, 64), B>>>(h1, W2, xw2, n);
    k_agg64<<<cdiv((long long)n * 32, B), B>>>(xw2, offs, bsrc, dinv,
                                               (const float2*)b2, h2, n);

    // ---- edge scores ----
    k_score<<<cdiv((long long)E * 8, B), B>>>(h2, src, dst, score, E);
}